// round 1
// baseline (speedup 1.0000x reference)
#include <cuda_runtime.h>
#include <math_constants.h>

#define BATCH  8
#define SLEN   1024
#define NHEAD  8
#define DMODEL 512
#define DKV    64
#define MROWS  (BATCH * SLEN)   // 8192

// Scratch (allocation-free: __device__ globals)
__device__ float g_q[BATCH * NHEAD * SLEN * DKV];    // [b,h,s,d]
__device__ float g_k[BATCH * NHEAD * SLEN * DKV];
__device__ float g_v[BATCH * NHEAD * SLEN * DKV];
__device__ float g_ctx[MROWS * DMODEL];              // [b*s, h*dv]

// ---------------------------------------------------------------------------
// GEMM + bias: C[M=8192, N=512] = A[8192,512] @ W[512,512]^T + bias
// MODE 0: A = g_ctx, write plain row-major to Cout (final projection)
// MODE 1/2/3: A = arg, write into g_q / g_k / g_v in [b,h,s,d] layout
// Tile: BM=128, BN=64, BK=16, 256 threads, 8x4 per thread.
// ---------------------------------------------------------------------------
template <int MODE>
__global__ __launch_bounds__(256) void gemm_bias_kernel(
    const float* __restrict__ Aarg, const float* __restrict__ W,
    const float* __restrict__ bias, float* __restrict__ Cout)
{
    const int K = DMODEL;
    const int N = DMODEL;
    const float* A = (MODE == 0) ? g_ctx : Aarg;

    __shared__ float As[16][128];  // transposed: As[k][m]
    __shared__ float Bs[16][64];   // transposed: Bs[k][n]

    const int tid = threadIdx.x;
    const int bm = blockIdx.y * 128;
    const int bn = blockIdx.x * 64;
    const int tx = tid & 15;        // 16 * 4 = 64 cols
    const int ty = tid >> 4;        // 16 * 8 = 128 rows
    const int lr = tid >> 2;        // 0..63 load row
    const int lk = (tid & 3) << 2;  // 0,4,8,12 load k

    float acc[8][4];
#pragma unroll
    for (int i = 0; i < 8; i++)
#pragma unroll
        for (int j = 0; j < 4; j++) acc[i][j] = 0.f;

    for (int k0 = 0; k0 < K; k0 += 16) {
        float4 a0 = *(const float4*)(A + (size_t)(bm + lr) * K + k0 + lk);
        float4 a1 = *(const float4*)(A + (size_t)(bm + lr + 64) * K + k0 + lk);
        float4 bv = *(const float4*)(W + (size_t)(bn + lr) * K + k0 + lk);
        As[lk + 0][lr] = a0.x; As[lk + 1][lr] = a0.y;
        As[lk + 2][lr] = a0.z; As[lk + 3][lr] = a0.w;
        As[lk + 0][lr + 64] = a1.x; As[lk + 1][lr + 64] = a1.y;
        As[lk + 2][lr + 64] = a1.z; As[lk + 3][lr + 64] = a1.w;
        Bs[lk + 0][lr] = bv.x; Bs[lk + 1][lr] = bv.y;
        Bs[lk + 2][lr] = bv.z; Bs[lk + 3][lr] = bv.w;
        __syncthreads();

#pragma unroll
        for (int kk = 0; kk < 16; kk++) {
            float4 aA = *(const float4*)&As[kk][ty * 8];
            float4 aB = *(const float4*)&As[kk][ty * 8 + 4];
            float4 bB = *(const float4*)&Bs[kk][tx * 4];
            float a[8] = {aA.x, aA.y, aA.z, aA.w, aB.x, aB.y, aB.z, aB.w};
            float b[4] = {bB.x, bB.y, bB.z, bB.w};
#pragma unroll
            for (int i = 0; i < 8; i++)
#pragma unroll
                for (int j = 0; j < 4; j++) acc[i][j] = fmaf(a[i], b[j], acc[i][j]);
        }
        __syncthreads();
    }

    const int col = bn + tx * 4;
    float4 bb = *(const float4*)(bias + col);
#pragma unroll
    for (int i = 0; i < 8; i++) {
        int row = bm + ty * 8 + i;
        float4 o;
        o.x = acc[i][0] + bb.x;
        o.y = acc[i][1] + bb.y;
        o.z = acc[i][2] + bb.z;
        o.w = acc[i][3] + bb.w;
        if (MODE == 0) {
            *(float4*)(Cout + (size_t)row * N + col) = o;
        } else {
            int b = row >> 10, s = row & 1023;
            int h = col >> 6, d = col & 63;
            float* dst = (MODE == 1) ? g_q : (MODE == 2) ? g_k : g_v;
            *(float4*)(dst + ((size_t)((b * NHEAD + h) * SLEN + s)) * DKV + d) = o;
        }
    }
}

// ---------------------------------------------------------------------------
// Flash-style attention: per block = (64-query tile, one (b,h)).
// Online softmax; mask folded in as s = masked ? -inf : s/8.
// 256 threads, each owns a 4x4 fragment. smem: Qt/Kt (d-major), Vs, Pt.
// ---------------------------------------------------------------------------
#define SPITCH 68
__global__ __launch_bounds__(256) void attn_kernel(const float* __restrict__ mask)
{
    extern __shared__ float smf[];
    float (*Qt)[SPITCH] = (float(*)[SPITCH])(smf);
    float (*Kt)[SPITCH] = (float(*)[SPITCH])(smf + 64 * SPITCH);
    float (*Vs)[SPITCH] = (float(*)[SPITCH])(smf + 2 * 64 * SPITCH);
    float (*Pt)[SPITCH] = (float(*)[SPITCH])(smf + 3 * 64 * SPITCH);

    const int tid = threadIdx.x;
    const int qt = blockIdx.x;   // 0..15
    const int bh = blockIdx.y;   // 0..63
    const int b = bh >> 3;
    const int h = bh & 7;

    const float* Q  = g_q + (size_t)bh * SLEN * DKV + (size_t)qt * 64 * DKV;
    const float* Kp = g_k + (size_t)bh * SLEN * DKV;
    const float* Vp = g_v + (size_t)bh * SLEN * DKV;
    const float* Mp = mask + (size_t)b * SLEN * SLEN + (size_t)qt * 64 * SLEN;

    const int tx = tid & 15;
    const int ty = tid >> 4;
    const int lr = tid >> 4;          // load row base 0..15
    const int lc = (tid & 15) * 4;    // load col 0..60

    // Load Q tile transposed (Qt[d][i] = Q[i][d])
#pragma unroll
    for (int it = 0; it < 4; it++) {
        int r = lr + it * 16;
        float4 qv = *(const float4*)(Q + (size_t)r * DKV + lc);
        Qt[lc + 0][r] = qv.x; Qt[lc + 1][r] = qv.y;
        Qt[lc + 2][r] = qv.z; Qt[lc + 3][r] = qv.w;
    }

    float m_i[4], l_i[4], acc[4][4];
#pragma unroll
    for (int i = 0; i < 4; i++) {
        m_i[i] = -1e30f; l_i[i] = 0.f;
#pragma unroll
        for (int j = 0; j < 4; j++) acc[i][j] = 0.f;
    }

    for (int kt = 0; kt < 16; kt++) {
        // Load K tile transposed + V tile direct
#pragma unroll
        for (int it = 0; it < 4; it++) {
            int r = lr + it * 16;
            float4 kv = *(const float4*)(Kp + (size_t)(kt * 64 + r) * DKV + lc);
            Kt[lc + 0][r] = kv.x; Kt[lc + 1][r] = kv.y;
            Kt[lc + 2][r] = kv.z; Kt[lc + 3][r] = kv.w;
            float4 vv = *(const float4*)(Vp + (size_t)(kt * 64 + r) * DKV + lc);
            *(float4*)&Vs[r][lc] = vv;
        }
        __syncthreads();

        // S = Q @ K^T (4x4 fragment per thread)
        float s[4][4];
#pragma unroll
        for (int i = 0; i < 4; i++)
#pragma unroll
            for (int j = 0; j < 4; j++) s[i][j] = 0.f;
#pragma unroll
        for (int d = 0; d < 64; d++) {
            float4 qa = *(const float4*)&Qt[d][ty * 4];
            float4 kb = *(const float4*)&Kt[d][tx * 4];
            float a[4] = {qa.x, qa.y, qa.z, qa.w};
            float bq[4] = {kb.x, kb.y, kb.z, kb.w};
#pragma unroll
            for (int i = 0; i < 4; i++)
#pragma unroll
                for (int j = 0; j < 4; j++) s[i][j] = fmaf(a[i], bq[j], s[i][j]);
        }

        // scale + mask (masked -> -inf, so exp contributes exactly 0)
#pragma unroll
        for (int i = 0; i < 4; i++) {
            float4 mv = *(const float4*)(Mp + (size_t)(ty * 4 + i) * SLEN + kt * 64 + tx * 4);
            s[i][0] = (mv.x != 0.f) ? -CUDART_INF_F : s[i][0] * 0.125f;
            s[i][1] = (mv.y != 0.f) ? -CUDART_INF_F : s[i][1] * 0.125f;
            s[i][2] = (mv.z != 0.f) ? -CUDART_INF_F : s[i][2] * 0.125f;
            s[i][3] = (mv.w != 0.f) ? -CUDART_INF_F : s[i][3] * 0.125f;
        }

        // Online softmax update per row
#pragma unroll
        for (int i = 0; i < 4; i++) {
            float rm = fmaxf(fmaxf(s[i][0], s[i][1]), fmaxf(s[i][2], s[i][3]));
#pragma unroll
            for (int off = 8; off >= 1; off >>= 1)
                rm = fmaxf(rm, __shfl_xor_sync(0xffffffffu, rm, off, 16));
            float mnew = fmaxf(fmaxf(m_i[i], rm), -1e30f);
            float sc = __expf(m_i[i] - mnew);
            float rs = 0.f;
#pragma unroll
            for (int j = 0; j < 4; j++) {
                float p = __expf(s[i][j] - mnew);
                s[i][j] = p;
                rs += p;
            }
#pragma unroll
            for (int off = 8; off >= 1; off >>= 1)
                rs += __shfl_xor_sync(0xffffffffu, rs, off, 16);
            l_i[i] = l_i[i] * sc + rs;
            m_i[i] = mnew;
#pragma unroll
            for (int j = 0; j < 4; j++) acc[i][j] *= sc;
            // write P transposed (Pt[j][i])
#pragma unroll
            for (int j = 0; j < 4; j++) Pt[tx * 4 + j][ty * 4 + i] = s[i][j];
        }
        __syncthreads();

        // O += P @ V
#pragma unroll
        for (int j = 0; j < 64; j++) {
            float4 pa = *(const float4*)&Pt[j][ty * 4];
            float4 vb = *(const float4*)&Vs[j][tx * 4];
            float p[4] = {pa.x, pa.y, pa.z, pa.w};
            float vv[4] = {vb.x, vb.y, vb.z, vb.w};
#pragma unroll
            for (int i = 0; i < 4; i++)
#pragma unroll
                for (int c = 0; c < 4; c++) acc[i][c] = fmaf(p[i], vv[c], acc[i][c]);
        }
        __syncthreads();
    }

    // Normalize + write ctx[b, s, h*64+dv]
#pragma unroll
    for (int i = 0; i < 4; i++) {
        float r = (l_i[i] > 0.f) ? (1.f / l_i[i]) : 0.f;
        int srow = qt * 64 + ty * 4 + i;
        float4 o = {acc[i][0] * r, acc[i][1] * r, acc[i][2] * r, acc[i][3] * r};
        *(float4*)(g_ctx + ((size_t)(b * SLEN + srow)) * DMODEL + h * DKV + tx * 4) = o;
    }
}

// ---------------------------------------------------------------------------
extern "C" void kernel_launch(void* const* d_in, const int* in_sizes, int n_in,
                              void* d_out, int out_size)
{
    const float* inputs = (const float*)d_in[0];
    const float* mask   = (const float*)d_in[1];
    const float* wq = (const float*)d_in[2];
    const float* bq = (const float*)d_in[3];
    const float* wk = (const float*)d_in[4];
    const float* bk = (const float*)d_in[5];
    const float* wv = (const float*)d_in[6];
    const float* bv = (const float*)d_in[7];
    const float* wo = (const float*)d_in[8];
    const float* bo = (const float*)d_in[9];
    float* out = (float*)d_out;

    dim3 gg(DMODEL / 64, MROWS / 128);   // (8, 64)
    gemm_bias_kernel<1><<<gg, 256>>>(inputs, wq, bq, nullptr);
    gemm_bias_kernel<2><<<gg, 256>>>(inputs, wk, bk, nullptr);
    gemm_bias_kernel<3><<<gg, 256>>>(inputs, wv, bv, nullptr);

    const int attn_smem = 4 * 64 * SPITCH * (int)sizeof(float);  // 69632 B
    cudaFuncSetAttribute(attn_kernel, cudaFuncAttributeMaxDynamicSharedMemorySize, attn_smem);
    dim3 ga(SLEN / 64, BATCH * NHEAD);   // (16, 64)
    attn_kernel<<<ga, 256, attn_smem>>>(mask);

    gemm_bias_kernel<0><<<gg, 256>>>(nullptr, wo, bo, out);
}

// round 3
// speedup vs baseline: 2.3197x; 2.3197x over previous
#include <cuda_runtime.h>
#include <cuda_bf16.h>
#include <math_constants.h>
#include <cstdint>

#define BATCH  8
#define SLEN   1024
#define NHEAD  8
#define DMODEL 512
#define DKV    64
#define MROWS  (BATCH * SLEN)   // 8192

// ---------------------------------------------------------------------------
// Scratch (allocation-free: __device__ globals)
// ---------------------------------------------------------------------------
__device__ __nv_bfloat16 g_ah[MROWS * DMODEL];      // A hi (inputs, later ctx)
__device__ __nv_bfloat16 g_al[MROWS * DMODEL];      // A lo
__device__ __nv_bfloat16 g_wh[4 * DMODEL * DMODEL]; // wq|wk|wv|wo hi
__device__ __nv_bfloat16 g_wl[4 * DMODEL * DMODEL]; // wq|wk|wv|wo lo
__device__ __nv_bfloat16 g_qh[MROWS * DMODEL], g_ql[MROWS * DMODEL];  // [b,h,s,d]
__device__ __nv_bfloat16 g_kh[MROWS * DMODEL], g_kl[MROWS * DMODEL];
__device__ __nv_bfloat16 g_vh[MROWS * DMODEL], g_vl[MROWS * DMODEL];
__device__ uint32_t g_mbits[BATCH * SLEN * (SLEN / 32)];   // 1MB bitmask

// ---------------------------------------------------------------------------
// Baseline-ISA helpers (sm_80-era: ldmatrix / mma.sync / cp.async) — NOT
// arch-specific, so they survive the harness's plain sm_103 PTX target.
// ---------------------------------------------------------------------------
__device__ __forceinline__ uint32_t smem_u32(const void* p) {
    uint32_t a;
    asm("{ .reg .u64 t; cvta.to.shared.u64 t, %1; cvt.u32.u64 %0, t; }" : "=r"(a) : "l"(p));
    return a;
}
__device__ __forceinline__ void ldsm_x4(uint32_t& r0, uint32_t& r1, uint32_t& r2,
                                        uint32_t& r3, uint32_t addr) {
    asm volatile("ldmatrix.sync.aligned.m8n8.x4.shared.b16 {%0,%1,%2,%3}, [%4];"
                 : "=r"(r0), "=r"(r1), "=r"(r2), "=r"(r3) : "r"(addr));
}
__device__ __forceinline__ void ldsm_x2t(uint32_t& r0, uint32_t& r1, uint32_t addr) {
    asm volatile("ldmatrix.sync.aligned.m8n8.x2.trans.shared.b16 {%0,%1}, [%2];"
                 : "=r"(r0), "=r"(r1) : "r"(addr));
}
__device__ __forceinline__ void mma_bf16(float* c, uint32_t a0, uint32_t a1, uint32_t a2,
                                         uint32_t a3, uint32_t b0, uint32_t b1) {
    asm volatile("mma.sync.aligned.m16n8k16.row.col.f32.bf16.bf16.f32 "
                 "{%0,%1,%2,%3}, {%4,%5,%6,%7}, {%8,%9}, {%0,%1,%2,%3};"
                 : "+f"(c[0]), "+f"(c[1]), "+f"(c[2]), "+f"(c[3])
                 : "r"(a0), "r"(a1), "r"(a2), "r"(a3), "r"(b0), "r"(b1));
}
__device__ __forceinline__ void cpa16(uint32_t s, const void* g) {
    asm volatile("cp.async.cg.shared.global [%0], [%1], 16;" :: "r"(s), "l"(g));
}
#define CPA_COMMIT() asm volatile("cp.async.commit_group;" ::: "memory")
#define CPA_WAIT0()  asm volatile("cp.async.wait_group 0;" ::: "memory")

__device__ __forceinline__ uint32_t pack2h(__nv_bfloat16 lo, __nv_bfloat16 hi) {
    return ((uint32_t)__bfloat16_as_ushort(hi) << 16) | __bfloat16_as_ushort(lo);
}
// split (x,y) into packed hi-pair and lo-pair (low half = x = even column)
__device__ __forceinline__ void split2(float x, float y, uint32_t& hp, uint32_t& lp) {
    __nv_bfloat16 hx = __float2bfloat16(x), hy = __float2bfloat16(y);
    hp = pack2h(hx, hy);
    lp = pack2h(__float2bfloat16(x - __bfloat162float(hx)),
                __float2bfloat16(y - __bfloat162float(hy)));
}

// ---------------------------------------------------------------------------
// fp32 -> bf16 hi/lo split conversion
// ---------------------------------------------------------------------------
__global__ __launch_bounds__(256) void cvt_kernel(
    const float* __restrict__ src, __nv_bfloat16* __restrict__ hi,
    __nv_bfloat16* __restrict__ lo, int n4)
{
    int i = blockIdx.x * 256 + threadIdx.x;
    if (i >= n4) return;
    float4 v = ((const float4*)src)[i];
    uint32_t h0, l0, h1, l1;
    split2(v.x, v.y, h0, l0);
    split2(v.z, v.w, h1, l1);
    ((uint2*)hi)[i] = make_uint2(h0, h1);
    ((uint2*)lo)[i] = make_uint2(l0, l1);
}

// ---------------------------------------------------------------------------
// mask (fp32, !=0 means masked) -> bitmask words
// ---------------------------------------------------------------------------
__global__ __launch_bounds__(256) void maskbits_kernel(const float* __restrict__ mask, int nwords)
{
    int gw = (blockIdx.x * blockDim.x + threadIdx.x) >> 5;
    int lane = threadIdx.x & 31;
    int nw = (gridDim.x * blockDim.x) >> 5;
    for (int w = gw; w < nwords; w += nw) {
        float v = mask[(size_t)w * 32 + lane];
        uint32_t bits = __ballot_sync(0xffffffffu, v != 0.f);
        if (lane == 0) g_mbits[w] = bits;
    }
}

// ---------------------------------------------------------------------------
// bf16-split GEMM via mma.sync: C[8192,512] = A @ W^T + bias
// block 128x128, 8 warps (warp tile 32x64), KC=32, cp.async double-buffer.
// MODE 0: fp32 out.  MODE 1/2/3: bf16 hi/lo scatter to g_{q,k,v}{h,l} [b,h,s,d].
// ---------------------------------------------------------------------------
#define GKC 32
#define GROWB 80                    // padded row bytes (40 bf16)
#define GA_BYTES (128 * GROWB)      // 10240 per array
#define GBUF (4 * GA_BYTES)         // 40960 per stage
#define GEMM_SMEM (2 * GBUF)        // 81920

template <int MODE>
__global__ __launch_bounds__(256) void mm_kernel(
    const __nv_bfloat16* __restrict__ Ah, const __nv_bfloat16* __restrict__ Al,
    const __nv_bfloat16* __restrict__ Bh, const __nv_bfloat16* __restrict__ Bl,
    const float* __restrict__ bias, float* __restrict__ Cout)
{
    extern __shared__ char smem[];
    const uint32_t sb = smem_u32(smem);
    const int tid = threadIdx.x, lane = tid & 31, wid = tid >> 5;
    const int wm = wid >> 1, wn = wid & 1;
    const int bm = blockIdx.y * 128, bn = blockIdx.x * 128;

    float acc[2][8][4];
#pragma unroll
    for (int i = 0; i < 2; i++)
#pragma unroll
        for (int j = 0; j < 8; j++)
#pragma unroll
            for (int k = 0; k < 4; k++) acc[i][j][k] = 0.f;

    auto load_chunk = [&](int c, int st) {
        uint32_t dst = sb + st * GBUF;
        int k0 = c * GKC;
        const __nv_bfloat16* srcs[4] = {Ah, Al, Bh, Bl};
#pragma unroll
        for (int arr = 0; arr < 4; arr++) {
            int rb = (arr < 2) ? bm : bn;
            const __nv_bfloat16* S = srcs[arr];
#pragma unroll
            for (int it = 0; it < 2; it++) {
                int idx = tid + it * 256;          // 0..511
                int r = idx >> 2, cc = idx & 3;
                cpa16(dst + arr * GA_BYTES + r * GROWB + cc * 16,
                      S + (size_t)(rb + r) * DMODEL + k0 + cc * 8);
            }
        }
        CPA_COMMIT();
    };

    load_chunk(0, 0);
    CPA_WAIT0();
    __syncthreads();

    for (int c = 0; c < DMODEL / GKC; ++c) {
        int st = c & 1;
        if (c < DMODEL / GKC - 1) load_chunk(c + 1, st ^ 1);
        uint32_t base = sb + st * GBUF;

        uint32_t ah[2][2][4], al[2][2][4];   // [mf][kstep][4]
#pragma unroll
        for (int mf = 0; mf < 2; mf++)
#pragma unroll
            for (int ks = 0; ks < 2; ks++) {
                uint32_t row = wm * 32 + mf * 16 + (lane & 15);
                uint32_t col = ks * 32 + ((lane >> 4) << 4);
                ldsm_x4(ah[mf][ks][0], ah[mf][ks][1], ah[mf][ks][2], ah[mf][ks][3],
                        base + 0 * GA_BYTES + row * GROWB + col);
                ldsm_x4(al[mf][ks][0], al[mf][ks][1], al[mf][ks][2], al[mf][ks][3],
                        base + 1 * GA_BYTES + row * GROWB + col);
            }
#pragma unroll
        for (int nf = 0; nf < 8; nf++) {
            uint32_t row = wn * 64 + nf * 8 + (lane & 7);
            uint32_t col = (lane >> 3) << 4;   // 0,16,32,48 -> k 0-7,8-15,16-23,24-31
            uint32_t bh[4], bl[4];
            ldsm_x4(bh[0], bh[1], bh[2], bh[3], base + 2 * GA_BYTES + row * GROWB + col);
            ldsm_x4(bl[0], bl[1], bl[2], bl[3], base + 3 * GA_BYTES + row * GROWB + col);
#pragma unroll
            for (int ks = 0; ks < 2; ks++)
#pragma unroll
                for (int mf = 0; mf < 2; mf++) {
                    float* C = acc[mf][nf];
                    mma_bf16(C, ah[mf][ks][0], ah[mf][ks][1], ah[mf][ks][2], ah[mf][ks][3],
                             bh[2 * ks], bh[2 * ks + 1]);
                    mma_bf16(C, ah[mf][ks][0], ah[mf][ks][1], ah[mf][ks][2], ah[mf][ks][3],
                             bl[2 * ks], bl[2 * ks + 1]);
                    mma_bf16(C, al[mf][ks][0], al[mf][ks][1], al[mf][ks][2], al[mf][ks][3],
                             bh[2 * ks], bh[2 * ks + 1]);
                }
        }
        if (c < DMODEL / GKC - 1) CPA_WAIT0();
        __syncthreads();
    }

    // Epilogue
    const int q4 = lane & 3, r4 = lane >> 2;
#pragma unroll
    for (int mf = 0; mf < 2; mf++)
#pragma unroll
        for (int nf = 0; nf < 8; nf++) {
            int col = bn + wn * 64 + nf * 8 + q4 * 2;
            float2 bb = *(const float2*)(bias + col);
#pragma unroll
            for (int hh = 0; hh < 2; hh++) {
                int row = bm + wm * 32 + mf * 16 + r4 + hh * 8;
                float v0 = acc[mf][nf][2 * hh + 0] + bb.x;
                float v1 = acc[mf][nf][2 * hh + 1] + bb.y;
                if (MODE == 0) {
                    *(float2*)(Cout + (size_t)row * DMODEL + col) = make_float2(v0, v1);
                } else {
                    int b = row >> 10, s = row & 1023, hd = col >> 6, d = col & 63;
                    size_t o = ((size_t)((b * NHEAD + hd) * SLEN + s)) * DKV + d;
                    uint32_t hp, lp;
                    split2(v0, v1, hp, lp);
                    __nv_bfloat16* dh = (MODE == 1) ? g_qh : (MODE == 2) ? g_kh : g_vh;
                    __nv_bfloat16* dl = (MODE == 1) ? g_ql : (MODE == 2) ? g_kl : g_vl;
                    *(uint32_t*)(dh + o) = hp;
                    *(uint32_t*)(dl + o) = lp;
                }
            }
        }
}

// ---------------------------------------------------------------------------
// Flash attention via mma.sync, bf16 hi/lo split for QK^T and PV.
// Block: 64 q-rows x one (b,h). 4 warps, 16 q-rows each, full 64-col tiles.
// ---------------------------------------------------------------------------
#define AROWB 144                    // padded row bytes (72 bf16)
#define AT_BYTES (64 * AROWB)        // 9216 per array
#define ABUF (4 * AT_BYTES)          // Kh,Kl,Vh,Vl = 36864 per stage
#define ATTN_SMEM (2 * ABUF)         // 73728

__global__ __launch_bounds__(128) void attn_kernel()
{
    extern __shared__ char smem[];
    const uint32_t sb = smem_u32(smem);
    const int tid = threadIdx.x, lane = tid & 31, w = tid >> 5;
    const int q4 = lane & 3, r4 = lane >> 2;
    const int qt = blockIdx.x, bh = blockIdx.y;
    const int b = bh >> 3, h = bh & 7;

    const __nv_bfloat16* Qh = g_qh + (size_t)bh * SLEN * DKV + (size_t)qt * 64 * DKV;
    const __nv_bfloat16* Ql = g_ql + (size_t)bh * SLEN * DKV + (size_t)qt * 64 * DKV;
    const __nv_bfloat16* Kh = g_kh + (size_t)bh * SLEN * DKV;
    const __nv_bfloat16* Kl = g_kl + (size_t)bh * SLEN * DKV;
    const __nv_bfloat16* Vh = g_vh + (size_t)bh * SLEN * DKV;
    const __nv_bfloat16* Vl = g_vl + (size_t)bh * SLEN * DKV;

    // ---- stage Q into buffer 1 (arrays 0,1), extract fragments ----
    {
        uint32_t qb = sb + ABUF;
#pragma unroll
        for (int arr = 0; arr < 2; arr++) {
            const __nv_bfloat16* S = arr ? Ql : Qh;
#pragma unroll
            for (int it = 0; it < 4; it++) {
                int idx = tid + it * 128;      // 0..511
                int r = idx >> 3, cc = idx & 7;
                cpa16(qb + arr * AT_BYTES + r * AROWB + cc * 16, S + r * DKV + cc * 8);
            }
        }
        CPA_COMMIT();
        CPA_WAIT0();
        __syncthreads();
    }
    uint32_t qfh[4][4], qfl[4][4];
    {
        uint32_t qb = sb + ABUF;
        uint32_t row = w * 16 + (lane & 15);
#pragma unroll
        for (int ks = 0; ks < 4; ks++) {
            uint32_t col = ks * 32 + ((lane >> 4) << 4);
            ldsm_x4(qfh[ks][0], qfh[ks][1], qfh[ks][2], qfh[ks][3],
                    qb + 0 * AT_BYTES + row * AROWB + col);
            ldsm_x4(qfl[ks][0], qfl[ks][1], qfl[ks][2], qfl[ks][3],
                    qb + 1 * AT_BYTES + row * AROWB + col);
        }
    }

    auto load_tile = [&](int kt, int st) {
        uint32_t dst = sb + st * ABUF;
        const __nv_bfloat16* srcs[4] = {Kh + (size_t)kt * 64 * DKV, Kl + (size_t)kt * 64 * DKV,
                                        Vh + (size_t)kt * 64 * DKV, Vl + (size_t)kt * 64 * DKV};
#pragma unroll
        for (int arr = 0; arr < 4; arr++)
#pragma unroll
            for (int it = 0; it < 4; it++) {
                int idx = tid + it * 128;
                int r = idx >> 3, cc = idx & 7;
                cpa16(dst + arr * AT_BYTES + r * AROWB + cc * 16, srcs[arr] + r * DKV + cc * 8);
            }
        CPA_COMMIT();
    };

    load_tile(0, 0);     // writes buffer 0 (Q lives in buffer 1; disjoint)
    CPA_WAIT0();
    __syncthreads();     // also orders Q-frag reads before tile 1 overwrites buf 1

    float o[8][4];
#pragma unroll
    for (int j = 0; j < 8; j++)
#pragma unroll
        for (int k = 0; k < 4; k++) o[j][k] = 0.f;
    float m0 = -1e30f, m1 = -1e30f, l0 = 0.f, l1 = 0.f;

    const uint32_t* mrow0 = g_mbits + ((size_t)b * SLEN + qt * 64 + w * 16 + r4) * 32;
    const uint32_t* mrow1 = mrow0 + 8 * 32;

    for (int kt = 0; kt < 16; ++kt) {
        int st = kt & 1;
        if (kt < 15) load_tile(kt + 1, st ^ 1);
        uint32_t base = sb + st * ABUF;

        // ---- S = Q @ K^T (fp32 accum, 3-way split) ----
        float s[8][4];
#pragma unroll
        for (int j = 0; j < 8; j++)
#pragma unroll
            for (int k = 0; k < 4; k++) s[j][k] = 0.f;

#pragma unroll
        for (int nf = 0; nf < 8; nf++) {
            uint32_t row = nf * 8 + (lane & 7);
            uint32_t coff = (lane >> 3) << 4;
            uint32_t kh0[4], kh1[4], kl0[4], kl1[4];
            ldsm_x4(kh0[0], kh0[1], kh0[2], kh0[3], base + 0 * AT_BYTES + row * AROWB + coff);
            ldsm_x4(kh1[0], kh1[1], kh1[2], kh1[3], base + 0 * AT_BYTES + row * AROWB + 64 + coff);
            ldsm_x4(kl0[0], kl0[1], kl0[2], kl0[3], base + 1 * AT_BYTES + row * AROWB + coff);
            ldsm_x4(kl1[0], kl1[1], kl1[2], kl1[3], base + 1 * AT_BYTES + row * AROWB + 64 + coff);
#pragma unroll
            for (int ks = 0; ks < 4; ks++) {
                uint32_t* KH = (ks < 2) ? kh0 : kh1;
                uint32_t* KL = (ks < 2) ? kl0 : kl1;
                int kk = (ks & 1) * 2;
                mma_bf16(s[nf], qfh[ks][0], qfh[ks][1], qfh[ks][2], qfh[ks][3], KH[kk], KH[kk + 1]);
                mma_bf16(s[nf], qfh[ks][0], qfh[ks][1], qfh[ks][2], qfh[ks][3], KL[kk], KL[kk + 1]);
                mma_bf16(s[nf], qfl[ks][0], qfl[ks][1], qfl[ks][2], qfl[ks][3], KH[kk], KH[kk + 1]);
            }
        }

        // ---- mask + scale ----
        uint32_t w0a = mrow0[kt * 2], w0b = mrow0[kt * 2 + 1];
        uint32_t w1a = mrow1[kt * 2], w1b = mrow1[kt * 2 + 1];
        float rm0 = -CUDART_INF_F, rm1 = -CUDART_INF_F;
#pragma unroll
        for (int nf = 0; nf < 8; nf++) {
            int c = nf * 8 + q4 * 2;
            uint32_t wr0 = (c < 32) ? w0a : w0b;
            uint32_t wr1 = (c < 32) ? w1a : w1b;
            int sh = c & 31;
            s[nf][0] = ((wr0 >> sh) & 1) ? -CUDART_INF_F : s[nf][0] * 0.125f;
            s[nf][1] = ((wr0 >> (sh + 1)) & 1) ? -CUDART_INF_F : s[nf][1] * 0.125f;
            s[nf][2] = ((wr1 >> sh) & 1) ? -CUDART_INF_F : s[nf][2] * 0.125f;
            s[nf][3] = ((wr1 >> (sh + 1)) & 1) ? -CUDART_INF_F : s[nf][3] * 0.125f;
            rm0 = fmaxf(rm0, fmaxf(s[nf][0], s[nf][1]));
            rm1 = fmaxf(rm1, fmaxf(s[nf][2], s[nf][3]));
        }
        rm0 = fmaxf(rm0, __shfl_xor_sync(0xffffffffu, rm0, 1));
        rm0 = fmaxf(rm0, __shfl_xor_sync(0xffffffffu, rm0, 2));
        rm1 = fmaxf(rm1, __shfl_xor_sync(0xffffffffu, rm1, 1));
        rm1 = fmaxf(rm1, __shfl_xor_sync(0xffffffffu, rm1, 2));

        float mn0 = fmaxf(m0, rm0), mn1 = fmaxf(m1, rm1);
        float sc0 = __expf(m0 - mn0), sc1 = __expf(m1 - mn1);
        float rs0 = 0.f, rs1 = 0.f;
        uint32_t pH01[8], pH23[8], pL01[8], pL23[8];
#pragma unroll
        for (int nf = 0; nf < 8; nf++) {
            float p0 = __expf(s[nf][0] - mn0);
            float p1 = __expf(s[nf][1] - mn0);
            float p2 = __expf(s[nf][2] - mn1);
            float p3 = __expf(s[nf][3] - mn1);
            rs0 += p0 + p1;
            rs1 += p2 + p3;
            split2(p0, p1, pH01[nf], pL01[nf]);
            split2(p2, p3, pH23[nf], pL23[nf]);
        }
        rs0 += __shfl_xor_sync(0xffffffffu, rs0, 1);
        rs0 += __shfl_xor_sync(0xffffffffu, rs0, 2);
        rs1 += __shfl_xor_sync(0xffffffffu, rs1, 1);
        rs1 += __shfl_xor_sync(0xffffffffu, rs1, 2);
        l0 = l0 * sc0 + rs0;
        l1 = l1 * sc1 + rs1;
        m0 = mn0;
        m1 = mn1;
#pragma unroll
        for (int nf = 0; nf < 8; nf++) {
            o[nf][0] *= sc0;
            o[nf][1] *= sc0;
            o[nf][2] *= sc1;
            o[nf][3] *= sc1;
        }

        // ---- O += P @ V  (P frags from registers; V via ldmatrix.trans) ----
#pragma unroll
        for (int ks = 0; ks < 4; ks++) {
            uint32_t a0 = pH01[2 * ks], a1 = pH23[2 * ks];
            uint32_t a2 = pH01[2 * ks + 1], a3 = pH23[2 * ks + 1];
            uint32_t la0 = pL01[2 * ks], la1 = pL23[2 * ks];
            uint32_t la2 = pL01[2 * ks + 1], la3 = pL23[2 * ks + 1];
            uint32_t vrow = ks * 16 + (lane & 15);
#pragma unroll
            for (int nf = 0; nf < 8; nf++) {
                uint32_t vh0, vh1, vl0, vl1;
                ldsm_x2t(vh0, vh1, base + 2 * AT_BYTES + vrow * AROWB + nf * 16);
                ldsm_x2t(vl0, vl1, base + 3 * AT_BYTES + vrow * AROWB + nf * 16);
                mma_bf16(o[nf], a0, a1, a2, a3, vh0, vh1);
                mma_bf16(o[nf], a0, a1, a2, a3, vl0, vl1);
                mma_bf16(o[nf], la0, la1, la2, la3, vh0, vh1);
            }
        }

        if (kt < 15) CPA_WAIT0();
        __syncthreads();
    }

    // ---- epilogue: ctx = O / l -> bf16 hi/lo into g_ah/g_al [row][h*64+d] ----
    float il0 = (l0 > 0.f) ? (1.f / l0) : 0.f;
    float il1 = (l1 > 0.f) ? (1.f / l1) : 0.f;
    int row0 = qt * 64 + w * 16 + r4;
#pragma unroll
    for (int nf = 0; nf < 8; nf++) {
        int col = h * 64 + nf * 8 + q4 * 2;
        uint32_t hp, lp;
        split2(o[nf][0] * il0, o[nf][1] * il0, hp, lp);
        *(uint32_t*)(g_ah + (size_t)(b * SLEN + row0) * DMODEL + col) = hp;
        *(uint32_t*)(g_al + (size_t)(b * SLEN + row0) * DMODEL + col) = lp;
        split2(o[nf][2] * il1, o[nf][3] * il1, hp, lp);
        *(uint32_t*)(g_ah + (size_t)(b * SLEN + row0 + 8) * DMODEL + col) = hp;
        *(uint32_t*)(g_al + (size_t)(b * SLEN + row0 + 8) * DMODEL + col) = lp;
    }
}

// ---------------------------------------------------------------------------
extern "C" void kernel_launch(void* const* d_in, const int* in_sizes, int n_in,
                              void* d_out, int out_size)
{
    const float* inputs = (const float*)d_in[0];
    const float* mask   = (const float*)d_in[1];
    const float* wq = (const float*)d_in[2];
    const float* bq = (const float*)d_in[3];
    const float* wk = (const float*)d_in[4];
    const float* bk = (const float*)d_in[5];
    const float* wv = (const float*)d_in[6];
    const float* bv = (const float*)d_in[7];
    const float* wo = (const float*)d_in[8];
    const float* bo = (const float*)d_in[9];
    float* out = (float*)d_out;

    __nv_bfloat16 *ah, *al, *wh, *wl;
    cudaGetSymbolAddress((void**)&ah, g_ah);
    cudaGetSymbolAddress((void**)&al, g_al);
    cudaGetSymbolAddress((void**)&wh, g_wh);
    cudaGetSymbolAddress((void**)&wl, g_wl);
    const int WSZ = DMODEL * DMODEL;

    cvt_kernel<<<(MROWS * DMODEL / 4 + 255) / 256, 256>>>(inputs, ah, al, MROWS * DMODEL / 4);
    cvt_kernel<<<(WSZ / 4 + 255) / 256, 256>>>(wq, wh + 0 * WSZ, wl + 0 * WSZ, WSZ / 4);
    cvt_kernel<<<(WSZ / 4 + 255) / 256, 256>>>(wk, wh + 1 * WSZ, wl + 1 * WSZ, WSZ / 4);
    cvt_kernel<<<(WSZ / 4 + 255) / 256, 256>>>(wv, wh + 2 * WSZ, wl + 2 * WSZ, WSZ / 4);
    cvt_kernel<<<(WSZ / 4 + 255) / 256, 256>>>(wo, wh + 3 * WSZ, wl + 3 * WSZ, WSZ / 4);
    maskbits_kernel<<<256, 256>>>(mask, BATCH * SLEN * (SLEN / 32));

    cudaFuncSetAttribute(mm_kernel<0>, cudaFuncAttributeMaxDynamicSharedMemorySize, GEMM_SMEM);
    cudaFuncSetAttribute(mm_kernel<1>, cudaFuncAttributeMaxDynamicSharedMemorySize, GEMM_SMEM);
    cudaFuncSetAttribute(mm_kernel<2>, cudaFuncAttributeMaxDynamicSharedMemorySize, GEMM_SMEM);
    cudaFuncSetAttribute(mm_kernel<3>, cudaFuncAttributeMaxDynamicSharedMemorySize, GEMM_SMEM);
    cudaFuncSetAttribute(attn_kernel, cudaFuncAttributeMaxDynamicSharedMemorySize, ATTN_SMEM);

    dim3 gg(DMODEL / 128, MROWS / 128);   // (4, 64)
    mm_kernel<1><<<gg, 256, GEMM_SMEM>>>(ah, al, wh + 0 * WSZ, wl + 0 * WSZ, bq, nullptr);
    mm_kernel<2><<<gg, 256, GEMM_SMEM>>>(ah, al, wh + 1 * WSZ, wl + 1 * WSZ, bk, nullptr);
    mm_kernel<3><<<gg, 256, GEMM_SMEM>>>(ah, al, wh + 2 * WSZ, wl + 2 * WSZ, bv, nullptr);

    dim3 ga(SLEN / 64, BATCH * NHEAD);    // (16, 64)
    attn_kernel<<<ga, 128, ATTN_SMEM>>>();   // writes ctx hi/lo into g_ah/g_al

    mm_kernel<0><<<gg, 256, GEMM_SMEM>>>(ah, al, wh + 3 * WSZ, wl + 3 * WSZ, bo, out);
}